// round 1
// baseline (speedup 1.0000x reference)
#include <cuda_runtime.h>
#include <cuda_bf16.h>
#include <cstdint>

// Problem constants
#define BB 64
#define TT 128
#define DD 512
#define HH 30
#define TM 98
static constexpr float INV_TEMP = 1.0f / 0.07f;

// Scratch (device globals: no allocation allowed)
__device__ __align__(16) __nv_bfloat16 g_zbf[BB * TT * DD];    // bf16 copy of z_seq
__device__ __align__(16) __nv_bfloat16 g_cproj[BB * TT * DD];  // bf16 c_proj = c@W + b
__device__ __align__(16) __nv_bfloat16 g_Wt[DD * DD];          // bf16 W^T  ([n][p])
__device__ float g_partials[TM * HH];                          // per-(t,k) sums of (lse - pos)

// ---------------------------------------------------------------------------
// Helpers: ldmatrix / mma.sync (bf16, m16n8k16, row.col)
// ---------------------------------------------------------------------------
__device__ __forceinline__ uint32_t smem_u32(const void* p) {
    return (uint32_t)__cvta_generic_to_shared(p);
}

__device__ __forceinline__ void ldm_x4(uint32_t& a0, uint32_t& a1, uint32_t& a2,
                                       uint32_t& a3, uint32_t addr) {
    asm volatile("ldmatrix.sync.aligned.m8n8.x4.shared.b16 {%0,%1,%2,%3}, [%4];\n"
                 : "=r"(a0), "=r"(a1), "=r"(a2), "=r"(a3) : "r"(addr));
}

__device__ __forceinline__ void ldm_x2(uint32_t& b0, uint32_t& b1, uint32_t addr) {
    asm volatile("ldmatrix.sync.aligned.m8n8.x2.shared.b16 {%0,%1}, [%2];\n"
                 : "=r"(b0), "=r"(b1) : "r"(addr));
}

__device__ __forceinline__ void mma_bf16(float* c, uint32_t a0, uint32_t a1,
                                         uint32_t a2, uint32_t a3,
                                         uint32_t b0, uint32_t b1) {
    asm volatile(
        "mma.sync.aligned.m16n8k16.row.col.f32.bf16.bf16.f32 "
        "{%0,%1,%2,%3}, {%4,%5,%6,%7}, {%8,%9}, {%0,%1,%2,%3};\n"
        : "+f"(c[0]), "+f"(c[1]), "+f"(c[2]), "+f"(c[3])
        : "r"(a0), "r"(a1), "r"(a2), "r"(a3), "r"(b0), "r"(b1));
}

// ---------------------------------------------------------------------------
// Kernel: convert z_seq fp32 -> bf16
// ---------------------------------------------------------------------------
__global__ void k_convert_z(const float* __restrict__ z) {
    int i = blockIdx.x * blockDim.x + threadIdx.x;
    int idx = i * 4;
    if (idx < BB * TT * DD) {
        float4 v = *(const float4*)(z + idx);
        __nv_bfloat162 lo = __floats2bfloat162_rn(v.x, v.y);
        __nv_bfloat162 hi = __floats2bfloat162_rn(v.z, v.w);
        *(__nv_bfloat162*)(g_zbf + idx) = lo;
        *(__nv_bfloat162*)(g_zbf + idx + 2) = hi;
    }
}

// Kernel: transpose+convert W fp32 [p][n] -> bf16 g_Wt [n][p]
__global__ void k_convert_w(const float* __restrict__ W) {
    int i = blockIdx.x * blockDim.x + threadIdx.x;
    if (i < DD * DD) {
        int n = i >> 9;
        int p = i & 511;
        g_Wt[i] = __float2bfloat16(W[p * DD + n]);
    }
}

// ---------------------------------------------------------------------------
// Kernel: GEMM1 c_proj = c_seq @ W + b  (bf16 out)
// M = 8192 (b*T + t), N = 512, K = 512. CTA tile 64x64, K-chunk 64, 4 warps.
// ---------------------------------------------------------------------------
__global__ void k_gemm1(const float* __restrict__ C, const float* __restrict__ bias) {
    __shared__ __nv_bfloat16 sA[64 * 72];
    __shared__ __nv_bfloat16 sB[64 * 72];

    const int tid = threadIdx.x;
    const int w = tid >> 5;
    const int lane = tid & 31;
    const int g = lane >> 2;
    const int t4 = lane & 3;
    const int m0 = blockIdx.x * 64;
    const int n0 = blockIdx.y * 64;

    float acc[8][4];
#pragma unroll
    for (int nt = 0; nt < 8; nt++)
#pragma unroll
        for (int e = 0; e < 4; e++) acc[nt][e] = 0.f;

    const float4* C4 = (const float4*)C;

    for (int kc = 0; kc < 8; kc++) {
        __syncthreads();
        // Load A (c_seq fp32 -> bf16): 64 rows x 64 cols
#pragma unroll
        for (int it = 0; it < 8; it++) {
            int idx = tid + it * 128;        // 0..1023, 64x16 float4
            int r = idx >> 4, c4 = idx & 15;
            float4 v = C4[(size_t)(m0 + r) * 128 + kc * 16 + c4];
            int o = r * 72 + c4 * 4;
            sA[o + 0] = __float2bfloat16(v.x);
            sA[o + 1] = __float2bfloat16(v.y);
            sA[o + 2] = __float2bfloat16(v.z);
            sA[o + 3] = __float2bfloat16(v.w);
        }
        // Load B (g_Wt bf16, rows n): 64 rows x 64 cols
#pragma unroll
        for (int it = 0; it < 4; it++) {
            int idx = tid + it * 128;        // 0..511, 64x8 uint4
            int r = idx >> 3, c8 = idx & 7;
            uint4 v = *(const uint4*)(g_Wt + (size_t)(n0 + r) * DD + kc * 64 + c8 * 8);
            *(uint4*)(sB + r * 72 + c8 * 8) = v;
        }
        __syncthreads();

#pragma unroll
        for (int ks = 0; ks < 4; ks++) {
            uint32_t a0, a1, a2, a3;
            uint32_t aaddr = smem_u32(sA + (w * 16 + (lane & 15)) * 72 +
                                      ks * 16 + (lane >> 4) * 8);
            ldm_x4(a0, a1, a2, a3, aaddr);
#pragma unroll
            for (int nt = 0; nt < 8; nt++) {
                uint32_t b0, b1;
                uint32_t baddr = smem_u32(sB + (nt * 8 + (lane & 7)) * 72 +
                                          ks * 16 + ((lane >> 3) & 1) * 8);
                ldm_x2(b0, b1, baddr);
                mma_bf16(acc[nt], a0, a1, a2, a3, b0, b1);
            }
        }
    }

    // Epilogue: add bias, store bf16
    const int r0 = m0 + w * 16 + g;
#pragma unroll
    for (int nt = 0; nt < 8; nt++) {
        int col = n0 + nt * 8 + t4 * 2;
        float bv0 = bias[col], bv1 = bias[col + 1];
        __nv_bfloat162 p0 = __floats2bfloat162_rn(acc[nt][0] + bv0, acc[nt][1] + bv1);
        *(__nv_bfloat162*)(g_cproj + (size_t)r0 * DD + col) = p0;
        __nv_bfloat162 p1 = __floats2bfloat162_rn(acc[nt][2] + bv0, acc[nt][3] + bv1);
        *(__nv_bfloat162*)(g_cproj + (size_t)(r0 + 8) * DD + col) = p1;
    }
}

// ---------------------------------------------------------------------------
// Kernel: fused scores GEMM + logsumexp - diag
// Grid: (98, 5). CTA = 128 threads (4 warps). blockIdx.x = t, blockIdx.y = k-group (6 ks).
// SMEM: C_t resident (64x512 bf16, ld 520) + streamed Z chunk (64x128, ld 136).
// ---------------------------------------------------------------------------
#define K2_SMEM_BYTES 86016

__global__ void k_scores() {
    extern __shared__ char smem[];
    __nv_bfloat16* sC = (__nv_bfloat16*)smem;                  // 64*520*2 = 66560 B
    __nv_bfloat16* sZ = (__nv_bfloat16*)(smem + 66560);        // 64*136*2 = 17408 B
    float* sRed = (float*)(smem + 66560 + 17408);              // 4 floats

    const int t = blockIdx.x;
    const int kg = blockIdx.y;
    const int tid = threadIdx.x;
    const int w = tid >> 5;
    const int lane = tid & 31;
    const int g = lane >> 2;
    const int t4 = lane & 3;

    // Load resident C_t tile: rows i=0..63, cols p=0..511
#pragma unroll
    for (int it = 0; it < 32; it++) {
        int idx = tid + it * 128;           // 0..4095 -> 64 rows x 64 uint4
        int r = idx >> 6, cu = idx & 63;
        uint4 v = *(const uint4*)(g_cproj + ((size_t)r * TT + t) * DD + cu * 8);
        *(uint4*)(sC + r * 520 + cu * 8) = v;
    }
    __syncthreads();

    for (int kk = 0; kk < 6; kk++) {
        const int k = kg * 6 + kk + 1;      // 1..30
        const int s = t + k;                // < 128 always

        float acc[8][4];
#pragma unroll
        for (int nt = 0; nt < 8; nt++)
#pragma unroll
            for (int e = 0; e < 4; e++) acc[nt][e] = 0.f;

        for (int ch = 0; ch < 4; ch++) {
            __syncthreads();
            // Stream Z chunk: rows j=0..63, cols ch*128 .. +128
#pragma unroll
            for (int it = 0; it < 8; it++) {
                int idx = tid + it * 128;   // 0..1023 -> 64 rows x 16 uint4
                int r = idx >> 4, cu = idx & 15;
                uint4 v = *(const uint4*)(g_zbf + ((size_t)r * TT + s) * DD +
                                          ch * 128 + cu * 8);
                *(uint4*)(sZ + r * 136 + cu * 8) = v;
            }
            __syncthreads();

#pragma unroll
            for (int ks = 0; ks < 8; ks++) {
                uint32_t a0, a1, a2, a3;
                uint32_t aaddr = smem_u32(sC + (w * 16 + (lane & 15)) * 520 +
                                          ch * 128 + ks * 16 + (lane >> 4) * 8);
                ldm_x4(a0, a1, a2, a3, aaddr);
#pragma unroll
                for (int nt = 0; nt < 8; nt++) {
                    uint32_t b0, b1;
                    uint32_t baddr = smem_u32(sZ + (nt * 8 + (lane & 7)) * 136 +
                                              ks * 16 + ((lane >> 3) & 1) * 8);
                    ldm_x2(b0, b1, baddr);
                    mma_bf16(acc[nt], a0, a1, a2, a3, b0, b1);
                }
            }
        }

        // --- Epilogue: per-row logsumexp minus diagonal ---
        // Warp w owns rows i = w*16 + {g, g+8}; cols j = nt*8 + t4*2 + {0,1}
        float local = 0.f;

        // Row r0 = g (regs [0],[1])
        {
            float m = -3.4e38f;
#pragma unroll
            for (int nt = 0; nt < 8; nt++)
                m = fmaxf(m, fmaxf(acc[nt][0], acc[nt][1]));
            m = fmaxf(m, __shfl_xor_sync(0xffffffffu, m, 1));
            m = fmaxf(m, __shfl_xor_sync(0xffffffffu, m, 2));
            float se = 0.f;
#pragma unroll
            for (int nt = 0; nt < 8; nt++) {
                se += expf((acc[nt][0] - m) * INV_TEMP);
                se += expf((acc[nt][1] - m) * INV_TEMP);
            }
            se += __shfl_xor_sync(0xffffffffu, se, 1);
            se += __shfl_xor_sync(0xffffffffu, se, 2);
            float lse = m * INV_TEMP + logf(se);
            int i = w * 16 + g;             // global row == diag col
            int nt_d = i >> 3, c = i & 7;
            if (t4 == (c >> 1)) local += lse - acc[nt_d][c & 1] * INV_TEMP;
        }
        // Row r1 = g+8 (regs [2],[3])
        {
            float m = -3.4e38f;
#pragma unroll
            for (int nt = 0; nt < 8; nt++)
                m = fmaxf(m, fmaxf(acc[nt][2], acc[nt][3]));
            m = fmaxf(m, __shfl_xor_sync(0xffffffffu, m, 1));
            m = fmaxf(m, __shfl_xor_sync(0xffffffffu, m, 2));
            float se = 0.f;
#pragma unroll
            for (int nt = 0; nt < 8; nt++) {
                se += expf((acc[nt][2] - m) * INV_TEMP);
                se += expf((acc[nt][3] - m) * INV_TEMP);
            }
            se += __shfl_xor_sync(0xffffffffu, se, 1);
            se += __shfl_xor_sync(0xffffffffu, se, 2);
            float lse = m * INV_TEMP + logf(se);
            int i = w * 16 + g + 8;
            int nt_d = i >> 3, c = i & 7;
            if (t4 == (c >> 1)) local += lse - acc[nt_d][2 + (c & 1)] * INV_TEMP;
        }

        // Warp reduction, then cross-warp via SMEM (deterministic)
#pragma unroll
        for (int off = 16; off > 0; off >>= 1)
            local += __shfl_xor_sync(0xffffffffu, local, off);
        if (lane == 0) sRed[w] = local;
        __syncthreads();
        if (tid == 0)
            g_partials[t * HH + (k - 1)] = sRed[0] + sRed[1] + sRed[2] + sRed[3];
    }
}

// ---------------------------------------------------------------------------
// Kernel: final deterministic reduction -> scalar mean
// ---------------------------------------------------------------------------
__global__ void k_reduce(float* __restrict__ out) {
    __shared__ float sh[256];
    int tid = threadIdx.x;
    float ssum = 0.f;
    for (int i = tid; i < TM * HH; i += 256) ssum += g_partials[i];
    sh[tid] = ssum;
    __syncthreads();
    for (int off = 128; off > 0; off >>= 1) {
        if (tid < off) sh[tid] += sh[tid + off];
        __syncthreads();
    }
    if (tid == 0) out[0] = sh[0] / (float)(TM * HH * BB);
}

// ---------------------------------------------------------------------------
extern "C" void kernel_launch(void* const* d_in, const int* in_sizes, int n_in,
                              void* d_out, int out_size) {
    const float* z = (const float*)d_in[0];
    const float* c = (const float*)d_in[1];
    const float* W = (const float*)d_in[2];
    const float* bias = (const float*)d_in[3];
    float* out = (float*)d_out;
    (void)in_sizes; (void)n_in; (void)out_size;

    cudaFuncSetAttribute(k_scores, cudaFuncAttributeMaxDynamicSharedMemorySize,
                         K2_SMEM_BYTES);

    k_convert_z<<<(BB * TT * DD / 4 + 255) / 256, 256>>>(z);
    k_convert_w<<<(DD * DD + 511) / 512, 512>>>(W);
    k_gemm1<<<dim3(128, 8), 128>>>(c, bias);
    k_scores<<<dim3(TM, 5), 128, K2_SMEM_BYTES>>>();
    k_reduce<<<1, 256>>>(out);
}